// round 3
// baseline (speedup 1.0000x reference)
#include <cuda_runtime.h>
#include <cuda_bf16.h>

// Problem constants: B=16, C=3, H=256, window w=5 -> 246x246 x 120 shifts.
#define HH    256
#define WW    5
#define OUTD  246          // H - 2w
#define TX    32           // output tile width
#define TY    16           // output tile height
#define HX    (TX + 2*WW)  // 42 halo tile width
#define HY    (TY + 2*WW)  // 26 halo tile height
#define NTHR  512
#define GX    8            // ceil(246/32)
#define GY    16           // ceil(246/16)
#define NB    16
#define NBLOCKS (GX*GY*NB) // 2048

// Scratch for deterministic two-stage reduction (no cudaMalloc allowed).
__device__ float g_partials[NBLOCKS];

// Packed f32x2 add (Blackwell). ptxas will not auto-fuse; must come from PTX.
__device__ __forceinline__ unsigned long long f2_add(unsigned long long a,
                                                     unsigned long long b) {
    unsigned long long r;
    asm("add.rn.f32x2 %0, %1, %2;" : "=l"(r) : "l"(a), "l"(b));
    return r;
}

__global__ __launch_bounds__(NTHR, 2)
void contrast_loss_kernel(const float* __restrict__ gO,
                          const float* __restrict__ gS) {
    // Interleaved (orig, sim) pairs per channel: one LDS.64 serves both images.
    __shared__ unsigned long long sh[3][HY * HX];
    __shared__ float warp_sums[NTHR / 32];

    const int tid = threadIdx.x;
    const int b   = blockIdx.z;
    const int by0 = blockIdx.y * TY;
    const int bx0 = blockIdx.x * TX;

    // ---- load halo tile (guarded against image edge; OOB slots unused) ----
    const float* oB = gO + (size_t)b * 3 * HH * HH;
    const float* sB = gS + (size_t)b * 3 * HH * HH;
    for (int idx = tid; idx < 3 * HY * HX; idx += NTHR) {
        int c   = idx / (HY * HX);
        int rem = idx - c * (HY * HX);
        int r   = rem / HX;
        int col = rem - r * HX;
        int iy = by0 + r;
        int ix = bx0 + col;
        float vo = 0.f, vs = 0.f;
        if (iy < HH && ix < HH) {
            int off = (c * HH + iy) * HH + ix;
            vo = oB[off];
            vs = sB[off];
        }
        sh[c][rem] = (unsigned long long)__float_as_uint(vo)
                   | ((unsigned long long)__float_as_uint(vs) << 32);
    }
    __syncthreads();

    // ---- compute: one output pixel per thread ----
    const int px = tid & 31;
    const int py = tid >> 5;
    float total = 0.f;

    if ((by0 + py) < OUTD && (bx0 + px) < OUTD) {
        const unsigned long long SGN = 0x8000000080000000ULL;
        const unsigned long long ABSM = 0x7fffffff7fffffffULL;
        const int base = (py + WW) * HX + (px + WW);
        // Negated centers (hoisted): p - c == p + (-c); abs afterwards.
        const unsigned long long nc0 = sh[0][base] ^ SGN;
        const unsigned long long nc1 = sh[1][base] ^ SGN;
        const unsigned long long nc2 = sh[2][base] ^ SGN;

        // All 121 positions: the (0,0) term contributes exactly 0 (|c-c|=0
        // for both images -> |0-0|=0), so no center-skip branch is needed.
        for (int dy = 0; dy < 11; ++dy) {
            const int row = (py + dy) * HX + px;
            #pragma unroll
            for (int dx = 0; dx < 11; ++dx) {
                unsigned long long t0 = f2_add(nc0, sh[0][row + dx]) & ABSM;
                unsigned long long t1 = f2_add(nc1, sh[1][row + dx]) & ABSM;
                unsigned long long t2 = f2_add(nc2, sh[2][row + dx]) & ABSM;
                unsigned long long s  = f2_add(f2_add(t0, t1), t2);
                float sO = __uint_as_float((unsigned int)s);
                float sS = __uint_as_float((unsigned int)(s >> 32));
                total += fabsf(sO - sS);
            }
        }
    }

    // ---- deterministic block reduction ----
    #pragma unroll
    for (int o = 16; o > 0; o >>= 1)
        total += __shfl_xor_sync(0xffffffffu, total, o);
    if (px == 0) warp_sums[py] = total;
    __syncthreads();
    if (tid == 0) {
        float s = 0.f;
        #pragma unroll
        for (int i = 0; i < NTHR / 32; ++i) s += warp_sums[i];
        int blin = (blockIdx.z * GY + blockIdx.y) * GX + blockIdx.x;
        g_partials[blin] = s;
    }
}

__global__ void finalize_kernel(float* __restrict__ out) {
    __shared__ float sm[256];
    float s = 0.f;
    for (int i = threadIdx.x; i < NBLOCKS; i += 256) s += g_partials[i];
    sm[threadIdx.x] = s;
    __syncthreads();
    for (int o = 128; o > 0; o >>= 1) {
        if (threadIdx.x < o) sm[threadIdx.x] += sm[threadIdx.x + o];
        __syncthreads();
    }
    if (threadIdx.x == 0) {
        // mean over 16 * 246 * 246 * 120 = 116,190,720 entries
        out[0] = sm[0] * (1.0f / 116190720.0f);
    }
}

extern "C" void kernel_launch(void* const* d_in, const int* in_sizes, int n_in,
                              void* d_out, int out_size) {
    const float* orig = (const float*)d_in[0];
    const float* sim  = (const float*)d_in[1];
    float* out = (float*)d_out;

    dim3 grid(GX, GY, NB);
    contrast_loss_kernel<<<grid, NTHR>>>(orig, sim);
    finalize_kernel<<<1, 256>>>(out);
}

// round 5
// speedup vs baseline: 1.3298x; 1.3298x over previous
#include <cuda_runtime.h>
#include <cuda_bf16.h>

// B=16, C=3, H=256, w=5 -> 246x246 pixels x 120 shifts (the (0,0) term is
// identically zero, so we loop all 121 with no branch).
#define HH    256
#define WW    5
#define OUTD  246
#define TX    32            // tile width  (output)
#define TYT   32            // tile height (output)
#define KP    8             // vertical pixels per thread
#define NT    128           // 32 x 4 threads
#define HX    (TX  + 2*WW)  // 42
#define HY    (TYT + 2*WW)  // 42
#define GX    8             // ceil(246/32)
#define GY    8
#define NB    16
#define NBLOCKS (GX*GY*NB)  // 1024

typedef unsigned long long u64;

// Scratch for deterministic reduction (no cudaMalloc allowed).
__device__ float g_partials[NBLOCKS];
__device__ int   g_done = 0;

// Packed f32x2 add (ptxas never auto-fuses; must come from PTX).
__device__ __forceinline__ u64 f2_add(u64 a, u64 b) {
    u64 r;
    asm("add.rn.f32x2 %0, %1, %2;" : "=l"(r) : "l"(a), "l"(b));
    return r;
}

__global__ __launch_bounds__(NT, 4)
void contrast_loss_kernel(const float* __restrict__ gO,
                          const float* __restrict__ gS,
                          float* __restrict__ out) {
    // Interleaved (orig, sim) pairs: one LDS.64 feeds both images.
    __shared__ u64   sh[3][HY * HX];
    __shared__ float red[NT / 32];
    __shared__ int   last_flag;

    const int tid = threadIdx.x;
    const int b   = blockIdx.z;
    const int by0 = blockIdx.y * TYT;
    const int bx0 = blockIdx.x * TX;

    // ---- halo load (OOB slots zero-filled; never used by valid pixels) ----
    const float* oB = gO + (size_t)b * 3 * HH * HH;
    const float* sB = gS + (size_t)b * 3 * HH * HH;
    for (int idx = tid; idx < 3 * HY * HX; idx += NT) {
        int c   = idx / (HY * HX);
        int rem = idx - c * (HY * HX);
        int r   = rem / HX;
        int col = rem - r * HX;
        int iy = by0 + r, ix = bx0 + col;
        float vo = 0.f, vs = 0.f;
        if (iy < HH && ix < HH) {
            int off = (c * HH + iy) * HH + ix;
            vo = oB[off];
            vs = sB[off];
        }
        sh[c][rem] = (u64)__float_as_uint(vo)
                   | ((u64)__float_as_uint(vs) << 32);
    }
    __syncthreads();

    // ---- compute: KP vertical pixels per thread, column-streamed reuse ----
    const int px  = tid & 31;
    const int ty  = tid >> 5;     // 0..3
    const int ry0 = ty * KP;      // first output row in tile for this thread

    const u64 SGN  = 0x8000000080000000ULL;
    const u64 ABSM = 0x7fffffff7fffffffULL;

    u64 nc0[KP], nc1[KP], nc2[KP];     // negated centers (p - c == p + (-c))
    #pragma unroll
    for (int p = 0; p < KP; ++p) {
        int ci = (ry0 + p + WW) * HX + (px + WW);
        nc0[p] = sh[0][ci] ^ SGN;
        nc1[p] = sh[1][ci] ^ SGN;
        nc2[p] = sh[2][ci] ^ SGN;
    }
    float acc[KP];
    #pragma unroll
    for (int p = 0; p < KP; ++p) acc[p] = 0.f;

    for (int dx = 0; dx < 11; ++dx) {
        const int base = ry0 * HX + px + dx;
        // Each column element r serves shifts (p, dy=r-p): up to KP evals
        // per LDS.64 -> 4.9x less shared traffic than the naive form.
        #pragma unroll
        for (int r = 0; r < KP + 10; ++r) {
            const u64 v0 = sh[0][base + r * HX];
            const u64 v1 = sh[1][base + r * HX];
            const u64 v2 = sh[2][base + r * HX];
            #pragma unroll
            for (int p = 0; p < KP; ++p) {
                const int dy = r - p;
                if (dy >= 0 && dy <= 10) {     // compile-time pruned
                    u64 t0 = f2_add(nc0[p], v0) & ABSM;
                    u64 t1 = f2_add(nc1[p], v1) & ABSM;
                    u64 t2 = f2_add(nc2[p], v2) & ABSM;
                    u64 s  = f2_add(f2_add(t0, t1), t2);
                    float sO = __uint_as_float((unsigned)s);
                    float sS = __uint_as_float((unsigned)(s >> 32));
                    acc[p] += fabsf(sO - sS);
                }
            }
        }
    }

    // ---- per-thread validity + deterministic block reduction ----
    float total = 0.f;
    const bool colok = (bx0 + px) < OUTD;
    #pragma unroll
    for (int p = 0; p < KP; ++p)
        if (colok && (by0 + ry0 + p) < OUTD) total += acc[p];

    #pragma unroll
    for (int o = 16; o > 0; o >>= 1)
        total += __shfl_xor_sync(0xffffffffu, total, o);
    if (px == 0) red[ty] = total;
    __syncthreads();

    const int blin = (b * GY + blockIdx.y) * GX + blockIdx.x;
    if (tid == 0) {
        g_partials[blin] = red[0] + red[1] + red[2] + red[3];
        __threadfence();
        int v = atomicAdd(&g_done, 1);
        last_flag = (v == NBLOCKS - 1);
    }
    __syncthreads();

    // ---- fused finalize: last arriving block sums the fixed-order array ----
    if (last_flag) {
        __threadfence();
        float s = 0.f;
        for (int i = tid; i < NBLOCKS; i += NT)
            s += __ldcg(&g_partials[i]);
        #pragma unroll
        for (int o = 16; o > 0; o >>= 1)
            s += __shfl_xor_sync(0xffffffffu, s, o);
        if (px == 0) red[ty] = s;
        __syncthreads();
        if (tid == 0) {
            // mean over 16 * 246 * 246 * 120 = 116,190,720 entries
            out[0] = (red[0] + red[1] + red[2] + red[3]) * (1.0f / 116190720.0f);
            g_done = 0;   // reset for next (graph-replayed) launch
        }
    }
}

extern "C" void kernel_launch(void* const* d_in, const int* in_sizes, int n_in,
                              void* d_out, int out_size) {
    const float* orig = (const float*)d_in[0];
    const float* sim  = (const float*)d_in[1];
    float* out = (float*)d_out;

    dim3 grid(GX, GY, NB);
    contrast_loss_kernel<<<grid, NT>>>(orig, sim, out);
}

// round 6
// speedup vs baseline: 1.4066x; 1.0577x over previous
#include <cuda_runtime.h>
#include <cuda_bf16.h>

// B=16, C=3, H=256, w=5 -> 246x246 pixels x 120 shifts.
// Symmetry: pairT(a,a+d) identical for (a,d) and (a+d,-d)  =>  compute only the
// 60 half-space shifts D+ over interior centers (sum M), then
//   F = 2*M + P - N
// where N = pairs (a interior, a+d outside interior)  [double-counted in 2M]
//       P = pairs (a outside interior, a+d interior)  [missing from 2M]
// N and P are ~2% of terms, handled by 960 small correction blocks fused into
// the same launch. Deterministic: fixed strip enumeration + fixed-order finalize.
#define HH    256
#define WW    5
#define OUTD  246
#define TX    32
#define TYT   32
#define KP    8
#define NT    128
#define HX    (TX + 2*WW)    // 42
#define HY2   (TYT + WW + 1) // 38 rows loaded (need rows 0..36; 37 used)
#define HROWS 37
#define GX    8
#define GY    8
#define NB    16
#define NMAIN (GX*GY*NB)     // 1024
#define NCORR (NB*60)        // 960
#define NTOT  (NMAIN+NCORR)  // 1984

typedef unsigned long long u64;

__device__ float g_partials[NMAIN];
__device__ float g_corr[NCORR];
__device__ int   g_done = 0;

__device__ __forceinline__ u64 f2_add(u64 a, u64 b) {
    u64 r;
    asm("add.rn.f32x2 %0, %1, %2;" : "=l"(r) : "l"(a), "l"(b));
    return r;
}

// scalar pair term from global memory (correction path)
__device__ __forceinline__ float pair_term(const float* __restrict__ oB,
                                           const float* __restrict__ sB,
                                           int rA, int cA, int rB, int cB) {
    float sO = 0.f, sS = 0.f;
    #pragma unroll
    for (int c = 0; c < 3; ++c) {
        int offA = c * HH * HH + rA * HH + cA;
        int offB = c * HH * HH + rB * HH + cB;
        sO += fabsf(__ldg(oB + offA) - __ldg(oB + offB));
        sS += fabsf(__ldg(sB + offA) - __ldg(sB + offB));
    }
    return fabsf(sO - sS);
}

__global__ __launch_bounds__(NT, 5)
void contrast_loss_kernel(const float* __restrict__ gO,
                          const float* __restrict__ gS,
                          float* __restrict__ out) {
    __shared__ u64   sh[3][HROWS * HX];
    __shared__ float red[NT / 32];
    __shared__ int   last_flag;

    const int tid  = threadIdx.x;
    const int blin = blockIdx.x;
    const int px   = tid & 31;
    const int ty   = tid >> 5;

    const u64 SGN  = 0x8000000080000000ULL;
    const u64 ABSM = 0x7fffffff7fffffffULL;

    if (blin < NMAIN) {
        // ================= main tile path (half-space shifts) =================
        const int b   = blin >> 6;
        const int by0 = ((blin >> 3) & 7) * TYT;
        const int bx0 = (blin & 7) * TX;

        const float* oB = gO + (size_t)b * 3 * HH * HH;
        const float* sB = gS + (size_t)b * 3 * HH * HH;
        // smem row r = image row (5+by0+r); smem col c = image col (bx0+c)
        for (int idx = tid; idx < 3 * HROWS * HX; idx += NT) {
            int c   = idx / (HROWS * HX);
            int rem = idx - c * (HROWS * HX);
            int r   = rem / HX;
            int col = rem - r * HX;
            int iy = WW + by0 + r, ix = bx0 + col;
            float vo = 0.f, vs = 0.f;
            if (iy < HH && ix < HH) {
                int off = (c * HH + iy) * HH + ix;
                vo = oB[off];
                vs = sB[off];
            }
            sh[c][rem] = (u64)__float_as_uint(vo)
                       | ((u64)__float_as_uint(vs) << 32);
        }
        __syncthreads();

        const int ry0 = ty * KP;

        u64 nc0[KP], nc1[KP], nc2[KP];
        #pragma unroll
        for (int p = 0; p < KP; ++p) {
            int ci = (ry0 + p) * HX + (px + WW);
            nc0[p] = sh[0][ci] ^ SGN;
            nc1[p] = sh[1][ci] ^ SGN;
            nc2[p] = sh[2][ci] ^ SGN;
        }
        float acc[KP];
        #pragma unroll
        for (int p = 0; p < KP; ++p) acc[p] = 0.f;

        // ---- loop A: dx in [-5,0], dy in [1,5] ----
        for (int dx = -5; dx <= 0; ++dx) {
            const int base = ry0 * HX + (px + WW + dx);
            #pragma unroll
            for (int rr = 1; rr <= 12; ++rr) {
                const u64 v0 = sh[0][base + rr * HX];
                const u64 v1 = sh[1][base + rr * HX];
                const u64 v2 = sh[2][base + rr * HX];
                #pragma unroll
                for (int p = 0; p < KP; ++p) {
                    const int dy = rr - p;
                    if (dy >= 1 && dy <= 5) {
                        u64 t0 = f2_add(nc0[p], v0) & ABSM;
                        u64 t1 = f2_add(nc1[p], v1) & ABSM;
                        u64 t2 = f2_add(nc2[p], v2) & ABSM;
                        u64 s  = f2_add(f2_add(t0, t1), t2);
                        float sO = __uint_as_float((unsigned)s);
                        float sS = __uint_as_float((unsigned)(s >> 32));
                        acc[p] += fabsf(sO - sS);
                    }
                }
            }
        }
        // ---- loop B: dx in [1,5], dy in [0,5] ----
        for (int dx = 1; dx <= 5; ++dx) {
            const int base = ry0 * HX + (px + WW + dx);
            #pragma unroll
            for (int rr = 0; rr <= 12; ++rr) {
                const u64 v0 = sh[0][base + rr * HX];
                const u64 v1 = sh[1][base + rr * HX];
                const u64 v2 = sh[2][base + rr * HX];
                #pragma unroll
                for (int p = 0; p < KP; ++p) {
                    const int dy = rr - p;
                    if (dy >= 0 && dy <= 5) {
                        u64 t0 = f2_add(nc0[p], v0) & ABSM;
                        u64 t1 = f2_add(nc1[p], v1) & ABSM;
                        u64 t2 = f2_add(nc2[p], v2) & ABSM;
                        u64 s  = f2_add(f2_add(t0, t1), t2);
                        float sO = __uint_as_float((unsigned)s);
                        float sS = __uint_as_float((unsigned)(s >> 32));
                        acc[p] += fabsf(sO - sS);
                    }
                }
            }
        }

        float total = 0.f;
        const bool colok = (bx0 + px) < OUTD;
        #pragma unroll
        for (int p = 0; p < KP; ++p)
            if (colok && (by0 + ry0 + p) < OUTD) total += acc[p];

        #pragma unroll
        for (int o = 16; o > 0; o >>= 1)
            total += __shfl_xor_sync(0xffffffffu, total, o);
        if (px == 0) red[ty] = total;
        __syncthreads();
        if (tid == 0)
            g_partials[blin] = red[0] + red[1] + red[2] + red[3];
    } else {
        // ================= correction path (P - N strips) =====================
        const int cid = blin - NMAIN;
        const int b   = cid / 60;
        const int s   = cid - b * 60;
        int i, j;
        if (s < 55) { i = 1 + s / 11; j = (s % 11) - 5; }
        else        { i = 0; j = s - 54; }
        const int aj = (j < 0) ? -j : j;

        const float* oB = gO + (size_t)b * 3 * HH * HH;
        const float* sB = gS + (size_t)b * 3 * HH * HH;

        const int n1 = i * OUTD;            // full-width row strip
        const int n2 = (OUTD - i) * aj;     // side strip
        const int n  = n1 + n2;

        float total = 0.f;
        for (int idx = tid; idx < 2 * n; idx += NT) {
            float sign;
            int ay, ax, by, bx;   // pair: A=(ay,ax), B=(by,bx), image coords
            if (idx < n) {
                // NEG: a interior, a+d outside interior  (subtract)
                sign = -1.f;
                int oy, ox;
                if (idx < n1) { oy = OUTD - i + idx / OUTD; ox = idx % OUTD; }
                else {
                    int t = idx - n1;
                    oy = t / aj;
                    int xo = t % aj;
                    ox = (j > 0) ? (OUTD - j + xo) : xo;
                }
                ay = WW + oy;     ax = WW + ox;
                by = ay + i;      bx = ax + j;
            } else {
                // POS: b interior, b-d outside interior  (add); pair (b-d, b)
                sign = 1.f;
                int k = idx - n;
                int oy, ox;
                if (k < n1) { oy = k / OUTD; ox = k % OUTD; }
                else {
                    int t = k - n1;
                    oy = i + t / aj;
                    int xo = t % aj;
                    ox = (j > 0) ? xo : (OUTD - aj + xo);
                }
                by = WW + oy;     bx = WW + ox;
                ay = by - i;      ax = bx - j;
            }
            total += sign * pair_term(oB, sB, ay, ax, by, bx);
        }

        #pragma unroll
        for (int o = 16; o > 0; o >>= 1)
            total += __shfl_xor_sync(0xffffffffu, total, o);
        if (px == 0) red[ty] = total;
        __syncthreads();
        if (tid == 0)
            g_corr[cid] = red[0] + red[1] + red[2] + red[3];
    }

    // ================= common epilogue: last block finalizes =================
    if (tid == 0) {
        __threadfence();
        int v = atomicAdd(&g_done, 1);
        last_flag = (v == NTOT - 1);
    }
    __syncthreads();

    if (last_flag) {
        __threadfence();
        float s = 0.f;
        for (int k = tid; k < NMAIN; k += NT) s += 2.0f * __ldcg(&g_partials[k]);
        for (int k = tid; k < NCORR; k += NT) s += __ldcg(&g_corr[k]);
        #pragma unroll
        for (int o = 16; o > 0; o >>= 1)
            s += __shfl_xor_sync(0xffffffffu, s, o);
        if (px == 0) red[ty] = s;
        __syncthreads();
        if (tid == 0) {
            // mean over 16 * 246 * 246 * 120 = 116,190,720 entries
            out[0] = (red[0] + red[1] + red[2] + red[3]) * (1.0f / 116190720.0f);
            g_done = 0;   // reset for graph replay
        }
    }
}

extern "C" void kernel_launch(void* const* d_in, const int* in_sizes, int n_in,
                              void* d_out, int out_size) {
    const float* orig = (const float*)d_in[0];
    const float* sim  = (const float*)d_in[1];
    float* out = (float*)d_out;

    contrast_loss_kernel<<<NTOT, NT>>>(orig, sim, out);
}